// round 15
// baseline (speedup 1.0000x reference)
#include <cuda_runtime.h>
#include <cuda_bf16.h>
#include <cuda_fp16.h>
#include <cstdint>

#define N_NODES 50000
#define N_EDGES 800000
#define N_GRAPHS 128
#define DIM 128
#define OUTD 64
#define BN_EPS 1e-5f

// ---------------- scratch (device globals; no runtime allocation) ----------------
__device__ uint32_t g_Hh[N_NODES * 64];     // H packed as half2 (4 elems / 8 B)
__device__ uint32_t g_Zh[N_NODES * 64];     // aggregated input, packed half2
__device__ uint32_t g_Z1h[N_NODES * 64];    // GEMM1 out (pre-BN1), packed half2
__device__ uint32_t g_Z2h[N_NODES * 64];    // GEMM2 out (pre-BN2), packed half2
__device__ float g_pooled[5 * N_GRAPHS * DIM];
__device__ float g_stats[8 * 256];          // per-GEMM: [0:128) sum, [128:256) sumsq
// weight fragments (single fp16): [mat8][kstep8][warp_n2][lane32][16 u32]
__device__ uint32_t g_WF[8 * 8192];
// CSR scratch
__device__ int g_deg[N_NODES];
__device__ int g_rowstart[N_NODES + 1];
__device__ int g_cursor[N_NODES];
__device__ int g_csr[N_EDGES];

// ---------------- helpers ----------------
__device__ __forceinline__ uint32_t smem_u32(const void* p) {
    uint32_t a;
    asm("{ .reg .u64 t; cvta.to.shared.u64 t, %1; cvt.u32.u64 %0, t; }" : "=r"(a) : "l"(p));
    return a;
}
__device__ __forceinline__ void red_add_f32x4(float* p, float4 v) {
    asm volatile("red.global.add.v4.f32 [%0], {%1,%2,%3,%4};"
                 :: "l"(p), "f"(v.x), "f"(v.y), "f"(v.z), "f"(v.w) : "memory");
}
__device__ __forceinline__ void ldmatrix_x4(uint32_t* r, uint32_t addr) {
    asm volatile("ldmatrix.sync.aligned.m8n8.x4.shared.b16 {%0,%1,%2,%3}, [%4];"
                 : "=r"(r[0]), "=r"(r[1]), "=r"(r[2]), "=r"(r[3]) : "r"(addr));
}
__device__ __forceinline__ void mma16816(float* c, const uint32_t* a, uint32_t b0, uint32_t b1) {
    asm volatile(
        "mma.sync.aligned.m16n8k16.row.col.f32.f16.f16.f32 "
        "{%0,%1,%2,%3}, {%4,%5,%6,%7}, {%8,%9}, {%0,%1,%2,%3};"
        : "+f"(c[0]), "+f"(c[1]), "+f"(c[2]), "+f"(c[3])
        : "r"(a[0]), "r"(a[1]), "r"(a[2]), "r"(a[3]), "r"(b0), "r"(b1));
}
__device__ __forceinline__ uint32_t pack_h2(float a, float b) {
    __half2 p = __floats2half2_rn(a, b);
    return *reinterpret_cast<uint32_t*>(&p);
}
__device__ __forceinline__ float2 unpack_h2(uint32_t w) {
    __half2 p = *reinterpret_cast<__half2*>(&w);
    return __half22float2(p);
}
__device__ __forceinline__ float4 u2_to_f4(uint2 u) {
    float2 a = unpack_h2(u.x), b = unpack_h2(u.y);
    return make_float4(a.x, a.y, b.x, b.y);
}
__device__ __forceinline__ float4 affine_relu(float4 v, float4 a4, float4 c4) {
    v.x = fmaxf(fmaf(v.x, a4.x, c4.x), 0.f);
    v.y = fmaxf(fmaf(v.y, a4.y, c4.y), 0.f);
    v.z = fmaxf(fmaf(v.z, a4.z, c4.z), 0.f);
    v.w = fmaxf(fmaf(v.w, a4.w, c4.w), 0.f);
    return v;
}

// ---------------- weight fragment pre-pack (single fp16) + zero stats/deg ----------
__global__ void conv_w_k(const float* __restrict__ W1, const float* __restrict__ W2,
                         uint32_t* __restrict__ WF, float* __restrict__ stats,
                         int* __restrict__ deg) {
    int gid = blockIdx.x * 256 + threadIdx.x;   // 65536 total (8 mats x 8192 words)
    if (gid < 2048) stats[gid] = 0.f;
    if (gid < N_NODES) deg[gid] = 0;
    int j    = gid & 15;
    int lane = (gid >> 4) & 31;
    int wn   = (gid >> 9) & 1;
    int ks   = (gid >> 10) & 7;
    int mat  = gid >> 13;
    const float* W = (mat < 4) ? (W1 + (size_t)mat * 16384)
                               : (W2 + (size_t)(mat - 4) * 16384);
    int k0 = ks * 16 + (lane & 3) * 2 + (j & 1) * 8;
    int n  = wn * 64 + (j >> 1) * 8 + (lane >> 2);
    float w0 = W[k0 * 128 + n];
    float w1 = W[(k0 + 1) * 128 + n];
    WF[(size_t)mat * 8192 + (size_t)ks * 1024 + (size_t)wn * 512 + (size_t)lane * 16 + j] =
        pack_h2(w0, w1);
}

// ---------------- GEMM: Ch[50000x128] = A' @ W, single fp16, fp32 accum ------------
// BM=128 tile, 391 CTAs, 512 threads (16 warps: wm=wid>>1 -> 16 rows, wn=wid&1 -> 64 cols).
// AFF=false: A is packed half2 -> direct swizzled copy.
// AFF=true:  A is packed half2; A' = relu(A*a+c) from stats_in, repacked fp16.
// Output C stored as packed half2. Epilogue accumulates per-column sum/sumsq
// (from exact fp32 accumulators) into stats_out.
template <bool AFF>
__global__ void __launch_bounds__(512)
gemm_mma_k(const uint32_t* __restrict__ Ah2, const uint4* __restrict__ WF4,
           uint32_t* __restrict__ C,
           const float* __restrict__ stats_in, const float* __restrict__ bng,
           const float* __restrict__ bnb, float* __restrict__ stats_out) {
    extern __shared__ __align__(16) unsigned char smraw[];
    uint4* As = reinterpret_cast<uint4*>(smraw);             // 128 rows x 16 uint4 (32 KB)
    float* sAff = reinterpret_cast<float*>(smraw + 32768);   // 256 floats

    const int t = threadIdx.x;
    const int lane = t & 31;
    const int wid = t >> 5;                 // 0..15
    const int wm = wid >> 1, wn = wid & 1;  // wm 0..7
    const int rowBase = blockIdx.x * 128;

    if (AFF) {
        if (t < 128) {
            const float invN = 1.0f / (float)N_NODES;
            float mean = stats_in[t] * invN;
            float var = stats_in[128 + t] * invN - mean * mean;
            float a = bng[t] * rsqrtf(var + BN_EPS);
            sAff[t] = a;
            sAff[128 + t] = bnb[t] - mean * a;
        }
        __syncthreads();
    }

    // ---- load A tile into swizzled smem (2048 16B-units / 512 threads = 4... 2 each x2) ----
#pragma unroll
    for (int jj = 0; jj < 4; ++jj) {
        int idx = t + jj * 512;
        if (idx >= 2048) break;
        int r = idx >> 4;
        int u = idx & 15;
        int grow = rowBase + r;
        uint4 w = make_uint4(0u, 0u, 0u, 0u);
        if (grow < N_NODES) {
            w = reinterpret_cast<const uint4*>(Ah2)[(size_t)grow * 16 + u];
            if (AFF) {
                const float4* S4 = reinterpret_cast<const float4*>(sAff);
                float4 f0 = affine_relu(u2_to_f4(make_uint2(w.x, w.y)), S4[u * 2], S4[32 + u * 2]);
                float4 f1 = affine_relu(u2_to_f4(make_uint2(w.z, w.w)), S4[u * 2 + 1], S4[32 + u * 2 + 1]);
                w = make_uint4(pack_h2(f0.x, f0.y), pack_h2(f0.z, f0.w),
                               pack_h2(f1.x, f1.y), pack_h2(f1.z, f1.w));
            }
        }
        int su = u ^ (r & 7);
        As[r * 16 + su] = w;
    }
    __syncthreads();

    // ---- mma mainloop: single fp16 pass, 16 rows x 64 cols per warp ----
    float acc[8][4];
#pragma unroll
    for (int nt = 0; nt < 8; ++nt)
#pragma unroll
        for (int i = 0; i < 4; ++i) acc[nt][i] = 0.f;

    const uint32_t AsB = smem_u32(As);
    const uint4* bp = WF4 + wn * 128 + lane * 4;   // per-lane B frags, uint4 index

#pragma unroll
    for (int ks = 0; ks < 8; ++ks) {
        uint32_t ah[4];
        {
            int row = wm * 16 + (lane & 15);
            int unit = ks * 2 + (lane >> 4);
            int su = unit ^ (row & 7);
            uint32_t off = (uint32_t)(row * 256 + su * 16);
            ldmatrix_x4(ah, AsB + off);
        }
#pragma unroll
        for (int p = 0; p < 4; ++p) {
            uint4 vh = __ldg(bp + ks * 256 + p);
            mma16816(acc[2 * p],     ah, vh.x, vh.y);
            mma16816(acc[2 * p + 1], ah, vh.z, vh.w);
        }
    }

    // ---- epilogue: C store (packed half2; 64 words per row) ----
    {
        int row = rowBase + wm * 16 + (lane >> 2);
        int colw = wn * 32 + (lane & 3);             // word index base (col/2)
        if (row < N_NODES) {
#pragma unroll
            for (int nt = 0; nt < 8; ++nt)
                C[(size_t)row * 64 + colw + nt * 4] = pack_h2(acc[nt][0], acc[nt][1]);
        }
        if (row + 8 < N_NODES) {
#pragma unroll
            for (int nt = 0; nt < 8; ++nt)
                C[(size_t)(row + 8) * 64 + colw + nt * 4] = pack_h2(acc[nt][2], acc[nt][3]);
        }
    }

    // ---- epilogue: column stats (zero-padded rows contribute 0 -> no masking) ----
    float ps[16], pq[16];
#pragma unroll
    for (int nt = 0; nt < 8; ++nt)
#pragma unroll
        for (int e = 0; e < 2; ++e) {
            int j = nt * 2 + e;
            float a0 = acc[nt][e], a1 = acc[nt][2 + e];
            ps[j] = a0 + a1;
            pq[j] = a0 * a0 + a1 * a1;
        }
#pragma unroll
    for (int off = 4; off < 32; off <<= 1)
#pragma unroll
        for (int j = 0; j < 16; ++j) {
            ps[j] += __shfl_xor_sync(0xFFFFFFFFu, ps[j], off);
            pq[j] += __shfl_xor_sync(0xFFFFFFFFu, pq[j], off);
        }
    __syncthreads();                       // smem A tile dead; reuse for reduction
    float* wbuf = reinterpret_cast<float*>(smraw);   // [2][16][64] = 2048 floats
    if (lane < 4) {
#pragma unroll
        for (int nt = 0; nt < 8; ++nt)
#pragma unroll
            for (int e = 0; e < 2; ++e) {
                int cl = nt * 8 + lane * 2 + e;
                wbuf[wid * 64 + cl] = ps[nt * 2 + e];
                wbuf[1024 + wid * 64 + cl] = pq[nt * 2 + e];
            }
    }
    __syncthreads();
    if (t < 256) {
        int st = t >> 7;                   // 0 = sum, 1 = sumsq
        int col = t & 127;
        int wn2 = col >> 6, cl = col & 63;
        float s = 0.f;
#pragma unroll
        for (int w = 0; w < 8; ++w) s += wbuf[st * 1024 + (w * 2 + wn2) * 64 + cl];
        atomicAdd(&stats_out[st * 128 + col], s);
    }
}

// ---------------- CSR build ----------------
__global__ void deg_k(const int* __restrict__ edst, int* __restrict__ deg) {
    int e = blockIdx.x * 256 + threadIdx.x;
    atomicAdd(&deg[edst[e]], 1);
}

// scan + cursor init; also zeroes pooled (folded memset, runs before pool_in_k)
__global__ void scan_k(const int* __restrict__ deg, int* __restrict__ rowstart,
                       int* __restrict__ cursor, float* __restrict__ pooled) {
    int t = threadIdx.x;
    float4* P4 = reinterpret_cast<float4*>(pooled);
#pragma unroll
    for (int i = 0; i < 20; ++i)
        P4[t + i * 1024] = make_float4(0.f, 0.f, 0.f, 0.f);

    __shared__ int ssum[1024];
    const int CH = (N_NODES + 1023) / 1024;   // 49
    int base = t * CH;
    int s = 0;
    for (int j = 0; j < CH; ++j) {
        int i = base + j;
        if (i < N_NODES) s += deg[i];
    }
    ssum[t] = s;
    __syncthreads();
    for (int off = 1; off < 1024; off <<= 1) {
        int v = (t >= off) ? ssum[t - off] : 0;
        __syncthreads();
        ssum[t] += v;
        __syncthreads();
    }
    int pre = (t == 0) ? 0 : ssum[t - 1];
    for (int j = 0; j < CH; ++j) {
        int i = base + j;
        if (i < N_NODES) {
            rowstart[i] = pre;
            cursor[i] = pre;
            pre += deg[i];
        }
    }
    if (t == 0) rowstart[N_NODES] = N_EDGES;
}

__global__ void fill_k(const int* __restrict__ esrc, const int* __restrict__ edst,
                       int* __restrict__ cursor, int* __restrict__ csr) {
    int e = blockIdx.x * 256 + threadIdx.x;
    int p = atomicAdd(&cursor[edst[e]], 1);
    csr[p] = esrc[e];
}

// ---------------- aggregation: Zh[node] = Hh[node] + sum_{s in CSR(node)} Hh[s] ----
// warp per node; lane handles 4 elems = uint2 of half2. fp32 accumulate, pack once.
__global__ void __launch_bounds__(256) agg_k(const uint32_t* __restrict__ Hh,
                                             const int* __restrict__ rs,
                                             const int* __restrict__ csr,
                                             uint32_t* __restrict__ Zh) {
    int gid = blockIdx.x * 256 + threadIdx.x;
    int node = gid >> 5;
    int lane = gid & 31;
    int s0 = __ldg(rs + node);
    int s1 = __ldg(rs + node + 1);
    uint2 w = reinterpret_cast<const uint2*>(Hh)[(size_t)node * 32 + lane];
    float2 p0 = unpack_h2(w.x), p1 = unpack_h2(w.y);
    float4 v = make_float4(p0.x, p0.y, p1.x, p1.y);
    for (int j = s0; j < s1; ++j) {
        int s = __ldg(csr + j);
        uint2 u = __ldg(reinterpret_cast<const uint2*>(Hh) + (size_t)s * 32 + lane);
        float2 q0 = unpack_h2(u.x), q1 = unpack_h2(u.y);
        v.x += q0.x; v.y += q0.y; v.z += q1.x; v.w += q1.y;
    }
    reinterpret_cast<uint2*>(Zh)[(size_t)node * 32 + lane] =
        make_uint2(pack_h2(v.x, v.y), pack_h2(v.z, v.w));
}

// ---------------- pool raw input h into pooled[0]; also emit packed fp16 h --------
__global__ void pool_in_k(const float* __restrict__ h, const int* __restrict__ gidx,
                          float* __restrict__ pooled, uint32_t* __restrict__ Hh) {
    int gid = blockIdx.x * 256 + threadIdx.x;
    int node = gid >> 5;
    int c = gid & 31;
    float4 v = reinterpret_cast<const float4*>(h)[(size_t)node * 32 + c];
    reinterpret_cast<uint2*>(Hh)[(size_t)node * 32 + c] =
        make_uint2(pack_h2(v.x, v.y), pack_h2(v.z, v.w));
    int gr = gidx[node];
    red_add_f32x4(pooled + (size_t)gr * DIM + c * 4, v);
}

// ---------------- v = relu(Zh*a + c) from raw stats; Hh = fp16(v); pooled += v -----
__global__ void pool_act_k(const uint32_t* __restrict__ Z2h, const float* __restrict__ stats,
                           const float* __restrict__ bng, const float* __restrict__ bnb,
                           const int* __restrict__ gidx, uint32_t* __restrict__ Hh,
                           float* __restrict__ pooled) {
    __shared__ float sa[256];
    int t = threadIdx.x;
    if (t < 128) {
        const float invN = 1.0f / (float)N_NODES;
        float mean = stats[t] * invN;
        float var = stats[128 + t] * invN - mean * mean;
        float a = bng[t] * rsqrtf(var + BN_EPS);
        sa[t] = a;
        sa[128 + t] = bnb[t] - mean * a;
    }
    __syncthreads();
    int gid = blockIdx.x * 256 + t;
    int node = gid >> 5;
    int c = gid & 31;
    float4 v = u2_to_f4(reinterpret_cast<const uint2*>(Z2h)[(size_t)node * 32 + c]);
    float4 a4 = reinterpret_cast<const float4*>(sa)[c];
    float4 c4 = reinterpret_cast<const float4*>(sa)[32 + c];
    v = affine_relu(v, a4, c4);
    reinterpret_cast<uint2*>(Hh)[(size_t)node * 32 + c] =
        make_uint2(pack_h2(v.x, v.y), pack_h2(v.z, v.w));
    int gr = gidx[node];
    red_add_f32x4(pooled + (size_t)gr * DIM + c * 4, v);
}

// ---------------- final score ----------------
__global__ void score_k(const float* __restrict__ pooled, const float* __restrict__ predW,
                        const float* __restrict__ predb, float* __restrict__ out) {
    int g = blockIdx.x;
    int o = threadIdx.x;
    __shared__ float sp[5 * DIM];
    for (int idx = o; idx < 5 * DIM; idx += 64)
        sp[idx] = pooled[(size_t)(idx / DIM) * (N_GRAPHS * DIM) + (size_t)g * DIM + (idx % DIM)];
    __syncthreads();
    float acc = 0.f;
#pragma unroll
    for (int i = 0; i < 5; ++i) acc += predb[i * OUTD + o];
    for (int i = 0; i < 5; ++i) {
#pragma unroll 4
        for (int k = 0; k < DIM; ++k)
            acc = fmaf(sp[i * DIM + k], predW[((size_t)i * DIM + k) * OUTD + o], acc);
    }
    out[(size_t)g * OUTD + o] = acc;
}

// ---------------- launch ----------------
extern "C" void kernel_launch(void* const* d_in, const int* in_sizes, int n_in,
                              void* d_out, int out_size) {
    const float* h     = (const float*)d_in[0];
    const int*   esrc  = (const int*)  d_in[1];
    const int*   edst  = (const int*)  d_in[2];
    const int*   gids  = (const int*)  d_in[3];
    const float* W1    = (const float*)d_in[4];
    const float* bn1_g = (const float*)d_in[5];
    const float* bn1_b = (const float*)d_in[6];
    const float* W2    = (const float*)d_in[7];
    const float* bn2_g = (const float*)d_in[8];
    const float* bn2_b = (const float*)d_in[9];
    const float* predW = (const float*)d_in[10];
    const float* predb = (const float*)d_in[11];
    float* out = (float*)d_out;

    float *pPooled, *pStats;
    uint32_t *pWF, *pHh, *pZh, *pZ1h, *pZ2h;
    int *pDeg, *pRS, *pCur, *pCSR;
    cudaGetSymbolAddress((void**)&pHh, g_Hh);
    cudaGetSymbolAddress((void**)&pZh, g_Zh);
    cudaGetSymbolAddress((void**)&pZ1h, g_Z1h);
    cudaGetSymbolAddress((void**)&pZ2h, g_Z2h);
    cudaGetSymbolAddress((void**)&pPooled, g_pooled);
    cudaGetSymbolAddress((void**)&pStats, g_stats);
    cudaGetSymbolAddress((void**)&pWF, g_WF);
    cudaGetSymbolAddress((void**)&pDeg, g_deg);
    cudaGetSymbolAddress((void**)&pRS, g_rowstart);
    cudaGetSymbolAddress((void**)&pCur, g_cursor);
    cudaGetSymbolAddress((void**)&pCSR, g_csr);

    const int GEMM_SMEM = 32768 + 1024;
    cudaFuncSetAttribute(gemm_mma_k<false>, cudaFuncAttributeMaxDynamicSharedMemorySize, GEMM_SMEM);
    cudaFuncSetAttribute(gemm_mma_k<true>,  cudaFuncAttributeMaxDynamicSharedMemorySize, GEMM_SMEM);

    const int NODE_BLOCKS = (N_NODES * 32) / 256;   // 6250
    const int EDGE_BLOCKS = N_EDGES / 256;          // 3125
    const int GEMM_BLOCKS = (N_NODES + 127) / 128;  // 391

    conv_w_k<<<256, 256>>>(W1, W2, pWF, pStats, pDeg);
    deg_k<<<EDGE_BLOCKS, 256>>>(edst, pDeg);
    scan_k<<<1, 1024>>>(pDeg, pRS, pCur, pPooled);
    fill_k<<<EDGE_BLOCKS, 256>>>(esrc, edst, pCur, pCSR);
    pool_in_k<<<NODE_BLOCKS, 256>>>(h, gids, pPooled, pHh);

    for (int i = 0; i < 4; ++i) {
        float* st1 = pStats + (size_t)(2 * i) * 256;
        float* st2 = pStats + (size_t)(2 * i + 1) * 256;

        agg_k<<<NODE_BLOCKS, 256>>>(pHh, pRS, pCSR, pZh);

        gemm_mma_k<false><<<GEMM_BLOCKS, 512, GEMM_SMEM>>>(
            pZh, (const uint4*)(pWF + (size_t)i * 8192), pZ1h,
            nullptr, nullptr, nullptr, st1);

        gemm_mma_k<true><<<GEMM_BLOCKS, 512, GEMM_SMEM>>>(
            pZ1h, (const uint4*)(pWF + (size_t)(4 + i) * 8192), pZ2h,
            st1, bn1_g + i * DIM, bn1_b + i * DIM, st2);

        pool_act_k<<<NODE_BLOCKS, 256>>>(pZ2h, st2, bn2_g + i * DIM, bn2_b + i * DIM,
                                         gids, pHh, pPooled + (size_t)(i + 1) * N_GRAPHS * DIM);
    }

    score_k<<<N_GRAPHS, OUTD>>>(pPooled, predW, predb, out);
}

// round 16
// speedup vs baseline: 1.1056x; 1.1056x over previous
#include <cuda_runtime.h>
#include <cuda_bf16.h>
#include <cuda_fp16.h>
#include <cstdint>

#define N_NODES 50000
#define N_EDGES 800000
#define N_GRAPHS 128
#define DIM 128
#define OUTD 64
#define BN_EPS 1e-5f

// ---------------- scratch (device globals; no runtime allocation) ----------------
__device__ uint32_t g_Hh[N_NODES * 64];     // H packed as half2 (4 elems / 8 B)
__device__ uint32_t g_Zh[N_NODES * 64];     // aggregated input, packed half2
__device__ uint32_t g_Z1h[N_NODES * 64];    // GEMM1 out (pre-BN1), packed half2
__device__ uint32_t g_Z2h[N_NODES * 64];    // GEMM2 out (pre-BN2), packed half2
__device__ float g_pooled[5 * N_GRAPHS * DIM];
__device__ float g_stats[8 * 256];          // per-GEMM: [0:128) sum, [128:256) sumsq
// weight fragments (single fp16): [mat8][kstep8][warp_n2][lane32][16 u32]
__device__ uint32_t g_WF[8 * 8192];
// CSR scratch
__device__ int g_deg[N_NODES];
__device__ int g_rowstart[N_NODES + 1];
__device__ int g_cursor[N_NODES];
__device__ int g_csr[N_EDGES];

// ---------------- helpers ----------------
__device__ __forceinline__ uint32_t smem_u32(const void* p) {
    uint32_t a;
    asm("{ .reg .u64 t; cvta.to.shared.u64 t, %1; cvt.u32.u64 %0, t; }" : "=r"(a) : "l"(p));
    return a;
}
__device__ __forceinline__ void red_add_f32x4(float* p, float4 v) {
    asm volatile("red.global.add.v4.f32 [%0], {%1,%2,%3,%4};"
                 :: "l"(p), "f"(v.x), "f"(v.y), "f"(v.z), "f"(v.w) : "memory");
}
__device__ __forceinline__ void ldmatrix_x4(uint32_t* r, uint32_t addr) {
    asm volatile("ldmatrix.sync.aligned.m8n8.x4.shared.b16 {%0,%1,%2,%3}, [%4];"
                 : "=r"(r[0]), "=r"(r[1]), "=r"(r[2]), "=r"(r[3]) : "r"(addr));
}
__device__ __forceinline__ void mma16816(float* c, const uint32_t* a, uint32_t b0, uint32_t b1) {
    asm volatile(
        "mma.sync.aligned.m16n8k16.row.col.f32.f16.f16.f32 "
        "{%0,%1,%2,%3}, {%4,%5,%6,%7}, {%8,%9}, {%0,%1,%2,%3};"
        : "+f"(c[0]), "+f"(c[1]), "+f"(c[2]), "+f"(c[3])
        : "r"(a[0]), "r"(a[1]), "r"(a[2]), "r"(a[3]), "r"(b0), "r"(b1));
}
__device__ __forceinline__ void cp_async16(uint32_t smem_dst, const void* gmem_src) {
    asm volatile("cp.async.ca.shared.global [%0], [%1], 16;"
                 :: "r"(smem_dst), "l"(gmem_src) : "memory");
}
__device__ __forceinline__ uint32_t pack_h2(float a, float b) {
    __half2 p = __floats2half2_rn(a, b);
    return *reinterpret_cast<uint32_t*>(&p);
}
__device__ __forceinline__ float2 unpack_h2(uint32_t w) {
    __half2 p = *reinterpret_cast<__half2*>(&w);
    return __half22float2(p);
}
__device__ __forceinline__ float4 u2_to_f4(uint2 u) {
    float2 a = unpack_h2(u.x), b = unpack_h2(u.y);
    return make_float4(a.x, a.y, b.x, b.y);
}
__device__ __forceinline__ float4 affine_relu(float4 v, float4 a4, float4 c4) {
    v.x = fmaxf(fmaf(v.x, a4.x, c4.x), 0.f);
    v.y = fmaxf(fmaf(v.y, a4.y, c4.y), 0.f);
    v.z = fmaxf(fmaf(v.z, a4.z, c4.z), 0.f);
    v.w = fmaxf(fmaf(v.w, a4.w, c4.w), 0.f);
    return v;
}

// ---------------- weight fragment pre-pack (single fp16) + zero stats/deg ----------
__global__ void conv_w_k(const float* __restrict__ W1, const float* __restrict__ W2,
                         uint32_t* __restrict__ WF, float* __restrict__ stats,
                         int* __restrict__ deg) {
    int gid = blockIdx.x * 256 + threadIdx.x;   // 65536 total (8 mats x 8192 words)
    if (gid < 2048) stats[gid] = 0.f;
    if (gid < N_NODES) deg[gid] = 0;
    int j    = gid & 15;
    int lane = (gid >> 4) & 31;
    int wn   = (gid >> 9) & 1;
    int ks   = (gid >> 10) & 7;
    int mat  = gid >> 13;
    const float* W = (mat < 4) ? (W1 + (size_t)mat * 16384)
                               : (W2 + (size_t)(mat - 4) * 16384);
    int k0 = ks * 16 + (lane & 3) * 2 + (j & 1) * 8;
    int n  = wn * 64 + (j >> 1) * 8 + (lane >> 2);
    float w0 = W[k0 * 128 + n];
    float w1 = W[(k0 + 1) * 128 + n];
    WF[(size_t)mat * 8192 + (size_t)ks * 1024 + (size_t)wn * 512 + (size_t)lane * 16 + j] =
        pack_h2(w0, w1);
}

// ---------------- GEMM: Ch[50000x128] = A' @ W, single fp16, fp32 accum ------------
// BM=128 tile: 391 CTAs, 256 threads (8 warps).
// AFF=false: A is packed half2 -> cp.async swizzled copy (no register round-trip).
// AFF=true:  A is packed half2; A' = relu(A*a+c) from stats_in, repacked fp16.
// Output C stored as packed half2. Epilogue accumulates per-column sum/sumsq
// (from exact fp32 accumulators) into stats_out.
template <bool AFF>
__global__ void __launch_bounds__(256)
gemm_mma_k(const uint32_t* __restrict__ Ah2, const uint4* __restrict__ WF4,
           uint32_t* __restrict__ C,
           const float* __restrict__ stats_in, const float* __restrict__ bng,
           const float* __restrict__ bnb, float* __restrict__ stats_out) {
    extern __shared__ __align__(16) unsigned char smraw[];
    uint4* As = reinterpret_cast<uint4*>(smraw);             // 128 rows x 16 uint4 (32 KB)
    float* sAff = reinterpret_cast<float*>(smraw + 32768);   // 256 floats

    const int t = threadIdx.x;
    const int lane = t & 31;
    const int wid = t >> 5;
    const int wm = wid >> 1, wn = wid & 1;
    const int rowBase = blockIdx.x * 128;

    if (AFF) {
        if (t < 128) {
            const float invN = 1.0f / (float)N_NODES;
            float mean = stats_in[t] * invN;
            float var = stats_in[128 + t] * invN - mean * mean;
            float a = bng[t] * rsqrtf(var + BN_EPS);
            sAff[t] = a;
            sAff[128 + t] = bnb[t] - mean * a;
        }
        __syncthreads();
    }

    // ---- load A tile into swizzled smem ----
    const uint32_t AsB = smem_u32(As);
#pragma unroll
    for (int jj = 0; jj < 8; ++jj) {
        int idx = t + jj * 256;        // 2048 16B-units
        int r = idx >> 4;
        int u = idx & 15;
        int grow = rowBase + r;
        int su = u ^ (r & 7);
        if (!AFF) {
            if (grow < N_NODES) {
                cp_async16(AsB + (uint32_t)((r * 16 + su) * 16),
                           reinterpret_cast<const uint4*>(Ah2) + (size_t)grow * 16 + u);
            } else {
                As[r * 16 + su] = make_uint4(0u, 0u, 0u, 0u);
            }
        } else {
            uint4 w = make_uint4(0u, 0u, 0u, 0u);
            if (grow < N_NODES) {
                w = reinterpret_cast<const uint4*>(Ah2)[(size_t)grow * 16 + u];
                const float4* S4 = reinterpret_cast<const float4*>(sAff);
                float4 f0 = affine_relu(u2_to_f4(make_uint2(w.x, w.y)), S4[u * 2], S4[32 + u * 2]);
                float4 f1 = affine_relu(u2_to_f4(make_uint2(w.z, w.w)), S4[u * 2 + 1], S4[32 + u * 2 + 1]);
                w = make_uint4(pack_h2(f0.x, f0.y), pack_h2(f0.z, f0.w),
                               pack_h2(f1.x, f1.y), pack_h2(f1.z, f1.w));
            }
            As[r * 16 + su] = w;
        }
    }
    if (!AFF) {
        asm volatile("cp.async.commit_group;" ::: "memory");
        asm volatile("cp.async.wait_group 0;" ::: "memory");
    }
    __syncthreads();

    // ---- mma mainloop: single fp16 pass ----
    float acc[2][8][4];
#pragma unroll
    for (int mt = 0; mt < 2; ++mt)
#pragma unroll
        for (int nt = 0; nt < 8; ++nt)
#pragma unroll
            for (int i = 0; i < 4; ++i) acc[mt][nt][i] = 0.f;

    const uint4* bp = WF4 + wn * 128 + lane * 4;   // per-lane B frags, uint4 index

#pragma unroll
    for (int ks = 0; ks < 8; ++ks) {
        uint32_t ah[2][4];
#pragma unroll
        for (int mt = 0; mt < 2; ++mt) {
            int row = wm * 32 + mt * 16 + (lane & 15);
            int unit = ks * 2 + (lane >> 4);
            int su = unit ^ (row & 7);
            uint32_t off = (uint32_t)(row * 256 + su * 16);
            ldmatrix_x4(ah[mt], AsB + off);
        }
#pragma unroll
        for (int p = 0; p < 4; ++p) {
            uint4 vh = __ldg(bp + ks * 256 + p);
            mma16816(acc[0][2 * p],     ah[0], vh.x, vh.y);
            mma16816(acc[1][2 * p],     ah[1], vh.x, vh.y);
            mma16816(acc[0][2 * p + 1], ah[0], vh.z, vh.w);
            mma16816(acc[1][2 * p + 1], ah[1], vh.z, vh.w);
        }
    }

    // ---- epilogue: C store (packed half2; 64 words per row) ----
#pragma unroll
    for (int mt = 0; mt < 2; ++mt) {
        int row = rowBase + wm * 32 + mt * 16 + (lane >> 2);
        int colw = wn * 32 + (lane & 3);             // word index base (col/2)
        if (row < N_NODES) {
#pragma unroll
            for (int nt = 0; nt < 8; ++nt)
                C[(size_t)row * 64 + colw + nt * 4] = pack_h2(acc[mt][nt][0], acc[mt][nt][1]);
        }
        if (row + 8 < N_NODES) {
#pragma unroll
            for (int nt = 0; nt < 8; ++nt)
                C[(size_t)(row + 8) * 64 + colw + nt * 4] = pack_h2(acc[mt][nt][2], acc[mt][nt][3]);
        }
    }

    // ---- epilogue: column stats (zero-padded rows contribute 0 -> no masking) ----
    float ps[16], pq[16];
#pragma unroll
    for (int nt = 0; nt < 8; ++nt)
#pragma unroll
        for (int e = 0; e < 2; ++e) {
            int j = nt * 2 + e;
            float a0 = acc[0][nt][e],     a1 = acc[0][nt][2 + e];
            float a2 = acc[1][nt][e],     a3 = acc[1][nt][2 + e];
            ps[j] = a0 + a1 + a2 + a3;
            pq[j] = a0 * a0 + a1 * a1 + a2 * a2 + a3 * a3;
        }
#pragma unroll
    for (int off = 4; off < 32; off <<= 1)
#pragma unroll
        for (int j = 0; j < 16; ++j) {
            ps[j] += __shfl_xor_sync(0xFFFFFFFFu, ps[j], off);
            pq[j] += __shfl_xor_sync(0xFFFFFFFFu, pq[j], off);
        }
    __syncthreads();                       // smem A tile dead; reuse for reduction
    float* wbuf = reinterpret_cast<float*>(smraw);   // [2][8][64]
    if (lane < 4) {
#pragma unroll
        for (int nt = 0; nt < 8; ++nt)
#pragma unroll
            for (int e = 0; e < 2; ++e) {
                int cl = nt * 8 + lane * 2 + e;
                wbuf[wid * 64 + cl] = ps[nt * 2 + e];
                wbuf[512 + wid * 64 + cl] = pq[nt * 2 + e];
            }
    }
    __syncthreads();
    {
        int st = t >> 7;                   // 0 = sum, 1 = sumsq
        int col = t & 127;
        int wn2 = col >> 6, cl = col & 63;
        float s = 0.f;
#pragma unroll
        for (int w = 0; w < 4; ++w) s += wbuf[st * 512 + (wn2 + 2 * w) * 64 + cl];
        atomicAdd(&stats_out[st * 128 + col], s);
    }
}

// ---------------- CSR build ----------------
__global__ void deg_k(const int* __restrict__ edst, int* __restrict__ deg) {
    int e = blockIdx.x * 256 + threadIdx.x;
    atomicAdd(&deg[edst[e]], 1);
}

// scan + cursor init; also zeroes pooled (folded memset, runs before pool_in_k)
__global__ void scan_k(const int* __restrict__ deg, int* __restrict__ rowstart,
                       int* __restrict__ cursor, float* __restrict__ pooled) {
    int t = threadIdx.x;
    float4* P4 = reinterpret_cast<float4*>(pooled);
#pragma unroll
    for (int i = 0; i < 20; ++i)
        P4[t + i * 1024] = make_float4(0.f, 0.f, 0.f, 0.f);

    __shared__ int ssum[1024];
    const int CH = (N_NODES + 1023) / 1024;   // 49
    int base = t * CH;
    int s = 0;
    for (int j = 0; j < CH; ++j) {
        int i = base + j;
        if (i < N_NODES) s += deg[i];
    }
    ssum[t] = s;
    __syncthreads();
    for (int off = 1; off < 1024; off <<= 1) {
        int v = (t >= off) ? ssum[t - off] : 0;
        __syncthreads();
        ssum[t] += v;
        __syncthreads();
    }
    int pre = (t == 0) ? 0 : ssum[t - 1];
    for (int j = 0; j < CH; ++j) {
        int i = base + j;
        if (i < N_NODES) {
            rowstart[i] = pre;
            cursor[i] = pre;
            pre += deg[i];
        }
    }
    if (t == 0) rowstart[N_NODES] = N_EDGES;
}

__global__ void fill_k(const int* __restrict__ esrc, const int* __restrict__ edst,
                       int* __restrict__ cursor, int* __restrict__ csr) {
    int e = blockIdx.x * 256 + threadIdx.x;
    int p = atomicAdd(&cursor[edst[e]], 1);
    csr[p] = esrc[e];
}

// ---------------- aggregation: Zh[node] = Hh[node] + sum_{s in CSR(node)} Hh[s] ----
// warp per node; lane handles 4 elems = uint2 of half2. fp32 accumulate, pack once.
__global__ void __launch_bounds__(256) agg_k(const uint32_t* __restrict__ Hh,
                                             const int* __restrict__ rs,
                                             const int* __restrict__ csr,
                                             uint32_t* __restrict__ Zh) {
    int gid = blockIdx.x * 256 + threadIdx.x;
    int node = gid >> 5;
    int lane = gid & 31;
    int s0 = __ldg(rs + node);
    int s1 = __ldg(rs + node + 1);
    uint2 w = reinterpret_cast<const uint2*>(Hh)[(size_t)node * 32 + lane];
    float2 p0 = unpack_h2(w.x), p1 = unpack_h2(w.y);
    float4 v = make_float4(p0.x, p0.y, p1.x, p1.y);
    for (int j = s0; j < s1; ++j) {
        int s = __ldg(csr + j);
        uint2 u = __ldg(reinterpret_cast<const uint2*>(Hh) + (size_t)s * 32 + lane);
        float2 q0 = unpack_h2(u.x), q1 = unpack_h2(u.y);
        v.x += q0.x; v.y += q0.y; v.z += q1.x; v.w += q1.y;
    }
    reinterpret_cast<uint2*>(Zh)[(size_t)node * 32 + lane] =
        make_uint2(pack_h2(v.x, v.y), pack_h2(v.z, v.w));
}

// ---------------- pool raw input h into pooled[0]; also emit packed fp16 h --------
__global__ void pool_in_k(const float* __restrict__ h, const int* __restrict__ gidx,
                          float* __restrict__ pooled, uint32_t* __restrict__ Hh) {
    int gid = blockIdx.x * 256 + threadIdx.x;
    int node = gid >> 5;
    int c = gid & 31;
    float4 v = reinterpret_cast<const float4*>(h)[(size_t)node * 32 + c];
    reinterpret_cast<uint2*>(Hh)[(size_t)node * 32 + c] =
        make_uint2(pack_h2(v.x, v.y), pack_h2(v.z, v.w));
    int gr = gidx[node];
    red_add_f32x4(pooled + (size_t)gr * DIM + c * 4, v);
}

// ---------------- v = relu(Zh*a + c) from raw stats; Hh = fp16(v); pooled += v -----
__global__ void pool_act_k(const uint32_t* __restrict__ Z2h, const float* __restrict__ stats,
                           const float* __restrict__ bng, const float* __restrict__ bnb,
                           const int* __restrict__ gidx, uint32_t* __restrict__ Hh,
                           float* __restrict__ pooled) {
    __shared__ float sa[256];
    int t = threadIdx.x;
    if (t < 128) {
        const float invN = 1.0f / (float)N_NODES;
        float mean = stats[t] * invN;
        float var = stats[128 + t] * invN - mean * mean;
        float a = bng[t] * rsqrtf(var + BN_EPS);
        sa[t] = a;
        sa[128 + t] = bnb[t] - mean * a;
    }
    __syncthreads();
    int gid = blockIdx.x * 256 + t;
    int node = gid >> 5;
    int c = gid & 31;
    float4 v = u2_to_f4(reinterpret_cast<const uint2*>(Z2h)[(size_t)node * 32 + c]);
    float4 a4 = reinterpret_cast<const float4*>(sa)[c];
    float4 c4 = reinterpret_cast<const float4*>(sa)[32 + c];
    v = affine_relu(v, a4, c4);
    reinterpret_cast<uint2*>(Hh)[(size_t)node * 32 + c] =
        make_uint2(pack_h2(v.x, v.y), pack_h2(v.z, v.w));
    int gr = gidx[node];
    red_add_f32x4(pooled + (size_t)gr * DIM + c * 4, v);
}

// ---------------- final score ----------------
__global__ void score_k(const float* __restrict__ pooled, const float* __restrict__ predW,
                        const float* __restrict__ predb, float* __restrict__ out) {
    int g = blockIdx.x;
    int o = threadIdx.x;
    __shared__ float sp[5 * DIM];
    for (int idx = o; idx < 5 * DIM; idx += 64)
        sp[idx] = pooled[(size_t)(idx / DIM) * (N_GRAPHS * DIM) + (size_t)g * DIM + (idx % DIM)];
    __syncthreads();
    float acc = 0.f;
#pragma unroll
    for (int i = 0; i < 5; ++i) acc += predb[i * OUTD + o];
    for (int i = 0; i < 5; ++i) {
#pragma unroll 4
        for (int k = 0; k < DIM; ++k)
            acc = fmaf(sp[i * DIM + k], predW[((size_t)i * DIM + k) * OUTD + o], acc);
    }
    out[(size_t)g * OUTD + o] = acc;
}

// ---------------- launch ----------------
extern "C" void kernel_launch(void* const* d_in, const int* in_sizes, int n_in,
                              void* d_out, int out_size) {
    const float* h     = (const float*)d_in[0];
    const int*   esrc  = (const int*)  d_in[1];
    const int*   edst  = (const int*)  d_in[2];
    const int*   gids  = (const int*)  d_in[3];
    const float* W1    = (const float*)d_in[4];
    const float* bn1_g = (const float*)d_in[5];
    const float* bn1_b = (const float*)d_in[6];
    const float* W2    = (const float*)d_in[7];
    const float* bn2_g = (const float*)d_in[8];
    const float* bn2_b = (const float*)d_in[9];
    const float* predW = (const float*)d_in[10];
    const float* predb = (const float*)d_in[11];
    float* out = (float*)d_out;

    float *pPooled, *pStats;
    uint32_t *pWF, *pHh, *pZh, *pZ1h, *pZ2h;
    int *pDeg, *pRS, *pCur, *pCSR;
    cudaGetSymbolAddress((void**)&pHh, g_Hh);
    cudaGetSymbolAddress((void**)&pZh, g_Zh);
    cudaGetSymbolAddress((void**)&pZ1h, g_Z1h);
    cudaGetSymbolAddress((void**)&pZ2h, g_Z2h);
    cudaGetSymbolAddress((void**)&pPooled, g_pooled);
    cudaGetSymbolAddress((void**)&pStats, g_stats);
    cudaGetSymbolAddress((void**)&pWF, g_WF);
    cudaGetSymbolAddress((void**)&pDeg, g_deg);
    cudaGetSymbolAddress((void**)&pRS, g_rowstart);
    cudaGetSymbolAddress((void**)&pCur, g_cursor);
    cudaGetSymbolAddress((void**)&pCSR, g_csr);

    const int GEMM_SMEM = 32768 + 1024;
    cudaFuncSetAttribute(gemm_mma_k<false>, cudaFuncAttributeMaxDynamicSharedMemorySize, GEMM_SMEM);
    cudaFuncSetAttribute(gemm_mma_k<true>,  cudaFuncAttributeMaxDynamicSharedMemorySize, GEMM_SMEM);

    const int NODE_BLOCKS = (N_NODES * 32) / 256;   // 6250
    const int EDGE_BLOCKS = N_EDGES / 256;          // 3125
    const int GEMM_BLOCKS = (N_NODES + 127) / 128;  // 391

    conv_w_k<<<256, 256>>>(W1, W2, pWF, pStats, pDeg);
    deg_k<<<EDGE_BLOCKS, 256>>>(edst, pDeg);
    scan_k<<<1, 1024>>>(pDeg, pRS, pCur, pPooled);
    fill_k<<<EDGE_BLOCKS, 256>>>(esrc, edst, pCur, pCSR);
    pool_in_k<<<NODE_BLOCKS, 256>>>(h, gids, pPooled, pHh);

    for (int i = 0; i < 4; ++i) {
        float* st1 = pStats + (size_t)(2 * i) * 256;
        float* st2 = pStats + (size_t)(2 * i + 1) * 256;

        agg_k<<<NODE_BLOCKS, 256>>>(pHh, pRS, pCSR, pZh);

        gemm_mma_k<false><<<GEMM_BLOCKS, 256, GEMM_SMEM>>>(
            pZh, (const uint4*)(pWF + (size_t)i * 8192), pZ1h,
            nullptr, nullptr, nullptr, st1);

        gemm_mma_k<true><<<GEMM_BLOCKS, 256, GEMM_SMEM>>>(
            pZ1h, (const uint4*)(pWF + (size_t)(4 + i) * 8192), pZ2h,
            st1, bn1_g + i * DIM, bn1_b + i * DIM, st2);

        pool_act_k<<<NODE_BLOCKS, 256>>>(pZ2h, st2, bn2_g + i * DIM, bn2_b + i * DIM,
                                         gids, pHh, pPooled + (size_t)(i + 1) * N_GRAPHS * DIM);
    }

    score_k<<<N_GRAPHS, OUTD>>>(pPooled, predW, predb, out);
}